// round 1
// baseline (speedup 1.0000x reference)
#include <cuda_runtime.h>
#include <math.h>

#define NMAX 100000
#define EMAX 800000
#define CDIM 128

// ---------------- scratch (static device globals; no runtime allocation) ----
__device__ int   g_count[NMAX];      // in-degree (excl self-loop)
__device__ float g_dis[NMAX];        // rsqrt(deg)
__device__ int   g_rowstart[NMAX];   // CSR row offsets (exclusive prefix)
__device__ int   g_cursor[NMAX];     // fill cursors
__device__ int   g_csr[EMAX];        // src ids grouped by dst
__device__ int   g_partial[1024];    // scan partials
__device__ float g_h[(size_t)NMAX * CDIM]; // propagated features

// ---------------- phase 1: degree ------------------------------------------
__global__ void k_zero(int n) {
    int i = blockIdx.x * blockDim.x + threadIdx.x;
    if (i < n) g_count[i] = 0;
}

__global__ void k_degree(const int* __restrict__ ei, int e) {
    int i = blockIdx.x * blockDim.x + threadIdx.x;
    if (i < e) atomicAdd(&g_count[ei[e + i]], 1);   // dst row
}

__global__ void k_dis(int n) {
    int i = blockIdx.x * blockDim.x + threadIdx.x;
    if (i < n) g_dis[i] = rsqrtf((float)(g_count[i] + 1));  // +1 self-loop
}

// ---------------- phase 2: scan -> CSR offsets ------------------------------
__global__ void k_partial(int n) {
    int t = threadIdx.x;                       // 1024 threads, 1 block
    int ch = (n + 1023) / 1024;
    int lo = t * ch, hi = min(lo + ch, n);
    int s = 0;
    for (int i = lo; i < hi; ++i) s += g_count[i];
    g_partial[t] = s;
}

__global__ void k_scan() {
    __shared__ int sm[1024];
    int t = threadIdx.x;
    sm[t] = g_partial[t];
    __syncthreads();
    for (int off = 1; off < 1024; off <<= 1) {
        int v = (t >= off) ? sm[t - off] : 0;
        __syncthreads();
        sm[t] += v;
        __syncthreads();
    }
    g_partial[t] = (t > 0) ? sm[t - 1] : 0;    // exclusive
}

__global__ void k_offsets(int n) {
    int t = threadIdx.x;
    int ch = (n + 1023) / 1024;
    int lo = t * ch, hi = min(lo + ch, n);
    int run = g_partial[t];
    for (int i = lo; i < hi; ++i) {
        g_rowstart[i] = run;
        g_cursor[i]   = run;
        run += g_count[i];
    }
}

__global__ void k_fill(const int* __restrict__ ei, int e) {
    int i = blockIdx.x * blockDim.x + threadIdx.x;
    if (i < e) {
        int s = ei[i];
        int d = ei[e + i];
        int pos = atomicAdd(&g_cursor[d], 1);
        g_csr[pos] = s;
    }
}

// ---------------- phase 3: gather SpMM (warp per node) ----------------------
__global__ void k_spmm(const float* __restrict__ x, int n, int e) {
    int warp = (blockIdx.x * blockDim.x + threadIdx.x) >> 5;
    if (warp >= n) return;
    int lane = threadIdx.x & 31;

    const float4* xr = (const float4*)x;
    float di = g_dis[warp];
    float4 a = xr[(size_t)warp * 32 + lane];
    float s2 = di * di;                              // self-loop norm
    float4 acc = make_float4(s2 * a.x, s2 * a.y, s2 * a.z, s2 * a.w);

    int start = g_rowstart[warp];
    int end   = (warp + 1 < n) ? g_rowstart[warp + 1] : e;
    for (int j = start; j < end; ++j) {
        int s = __ldg(&g_csr[j]);                    // uniform across warp
        float w = di * __ldg(&g_dis[s]);
        float4 v = xr[(size_t)s * 32 + lane];        // 512B coalesced, L2-hit
        acc.x += w * v.x; acc.y += w * v.y;
        acc.z += w * v.z; acc.w += w * v.w;
    }
    ((float4*)g_h)[(size_t)warp * 32 + lane] = acc;
}

// ---------------- phase 4: fused dual GEMM + epilogue ------------------------
// out = relu( c1*(h + x0) + BETA * ( h@W1 + x0@W2 ) )
// as a single [N,256] x [256,128] GEMM with A=[h|x0], B=[W1;W2].
__global__ __launch_bounds__(256, 2)
void k_gemm(const float* __restrict__ x0,
            const float* __restrict__ w1, const float* __restrict__ w2,
            float* __restrict__ out, int n) {
    __shared__ float sA[16][64];      // transposed: sA[k][m]
    __shared__ float sB[16][128];

    const float BETA = 0.6931471805599453f;
    const float C1   = 0.15342640972002733f;   // (1-a)(1-b) == a(1-b), a=0.5

    int tid = threadIdx.x;
    int bm  = blockIdx.x * 64;
    int tx  = tid & 15;          // 16 col-groups of 8
    int ty  = tid >> 4;          // 16 row-groups of 4
    int lr  = tid >> 2;          // loader row 0..63
    int lk  = (tid & 3) * 4;     // loader k offset 0,4,8,12
    int bk  = tid >> 5;          // B loader k 0..7
    int bj  = (tid & 31) * 4;    // B loader col

    float acc[4][8];
#pragma unroll
    for (int r = 0; r < 4; ++r)
#pragma unroll
        for (int q = 0; q < 8; ++q) acc[r][q] = 0.f;

    for (int k0 = 0; k0 < 256; k0 += 16) {
        const float* Ap; const float* Bp; int kk0;
        if (k0 < 128) { Ap = g_h; Bp = w1; kk0 = k0; }
        else          { Ap = x0;  Bp = w2; kk0 = k0 - 128; }

        // load A tile 64x16 (transposed into smem)
        int gi = bm + lr;
        float4 av = make_float4(0.f, 0.f, 0.f, 0.f);
        if (gi < n) av = *(const float4*)(Ap + (size_t)gi * CDIM + kk0 + lk);
        sA[lk + 0][lr] = av.x; sA[lk + 1][lr] = av.y;
        sA[lk + 2][lr] = av.z; sA[lk + 3][lr] = av.w;

        // load B tile 16x128
        *(float4*)&sB[bk][bj]     = *(const float4*)(Bp + (size_t)(kk0 + bk) * CDIM + bj);
        *(float4*)&sB[bk + 8][bj] = *(const float4*)(Bp + (size_t)(kk0 + bk + 8) * CDIM + bj);
        __syncthreads();

#pragma unroll
        for (int kk = 0; kk < 16; ++kk) {
            float a0 = sA[kk][ty * 4 + 0];
            float a1 = sA[kk][ty * 4 + 1];
            float a2 = sA[kk][ty * 4 + 2];
            float a3 = sA[kk][ty * 4 + 3];
            float4 b0 = *(float4*)&sB[kk][tx * 8];
            float4 b1 = *(float4*)&sB[kk][tx * 8 + 4];
            float bb[8] = {b0.x, b0.y, b0.z, b0.w, b1.x, b1.y, b1.z, b1.w};
#pragma unroll
            for (int q = 0; q < 8; ++q) {
                acc[0][q] += a0 * bb[q];
                acc[1][q] += a1 * bb[q];
                acc[2][q] += a2 * bb[q];
                acc[3][q] += a3 * bb[q];
            }
        }
        __syncthreads();
    }

    // epilogue
    int j0 = tx * 8;
#pragma unroll
    for (int r = 0; r < 4; ++r) {
        int i = bm + ty * 4 + r;
        if (i < n) {
            const float* hp = g_h + (size_t)i * CDIM + j0;
            const float* pp = x0  + (size_t)i * CDIM + j0;
            float4 h0 = *(const float4*)(hp);
            float4 h1 = *(const float4*)(hp + 4);
            float4 p0 = *(const float4*)(pp);
            float4 p1 = *(const float4*)(pp + 4);
            float4 o0, o1;
            o0.x = fmaxf(BETA * acc[r][0] + C1 * (h0.x + p0.x), 0.f);
            o0.y = fmaxf(BETA * acc[r][1] + C1 * (h0.y + p0.y), 0.f);
            o0.z = fmaxf(BETA * acc[r][2] + C1 * (h0.z + p0.z), 0.f);
            o0.w = fmaxf(BETA * acc[r][3] + C1 * (h0.w + p0.w), 0.f);
            o1.x = fmaxf(BETA * acc[r][4] + C1 * (h1.x + p1.x), 0.f);
            o1.y = fmaxf(BETA * acc[r][5] + C1 * (h1.y + p1.y), 0.f);
            o1.z = fmaxf(BETA * acc[r][6] + C1 * (h1.z + p1.z), 0.f);
            o1.w = fmaxf(BETA * acc[r][7] + C1 * (h1.w + p1.w), 0.f);
            *(float4*)(out + (size_t)i * CDIM + j0)     = o0;
            *(float4*)(out + (size_t)i * CDIM + j0 + 4) = o1;
        }
    }
}

// ---------------- launch -----------------------------------------------------
extern "C" void kernel_launch(void* const* d_in, const int* in_sizes, int n_in,
                              void* d_out, int out_size) {
    const float* x   = (const float*)d_in[0];
    const float* x0  = (const float*)d_in[1];
    const float* w1  = (const float*)d_in[2];
    const float* w2  = (const float*)d_in[3];
    const int*   ei  = (const int*)d_in[4];
    float* out = (float*)d_out;

    int n = in_sizes[0] / CDIM;      // 100000
    int e = in_sizes[4] / 2;         // 800000

    int nb = (n + 255) / 256;
    int eb = (e + 255) / 256;

    k_zero<<<nb, 256>>>(n);
    k_degree<<<eb, 256>>>(ei, e);
    k_dis<<<nb, 256>>>(n);
    k_partial<<<1, 1024>>>(n);
    k_scan<<<1, 1024>>>();
    k_offsets<<<1, 1024>>>(n);
    k_fill<<<eb, 256>>>(ei, e);

    int spmm_threads = n * 32;
    k_spmm<<<(spmm_threads + 255) / 256, 256>>>(x, n, e);

    k_gemm<<<(n + 63) / 64, 256>>>(x0, w1, w2, out, n);
}

// round 2
// speedup vs baseline: 1.9851x; 1.9851x over previous
#include <cuda_runtime.h>
#include <mma.h>
#include <math.h>

using namespace nvcuda;

#define NMAX 100000
#define EMAX 800000
#define CDIM 128

// ---------------- scratch (static device globals) ---------------------------
__device__ int   g_count[NMAX];
__device__ float g_dis[NMAX];
__device__ int   g_rowstart[NMAX];
__device__ int   g_cursor[NMAX];
__device__ int   g_csr[EMAX];
__device__ int   g_bsum[512];
__device__ int   g_bpre[512];
__device__ float g_h[(size_t)NMAX * CDIM];

// ---------------- phase 1: degree -------------------------------------------
__global__ void k_zero(int n) {
    int i = blockIdx.x * blockDim.x + threadIdx.x;
    if (i < n) g_count[i] = 0;
}

__global__ void k_degree(const int* __restrict__ ei, int e) {
    int i = blockIdx.x * blockDim.x + threadIdx.x;
    if (i < e) atomicAdd(&g_count[ei[e + i]], 1);   // dst
}

// ---------------- phase 2: parallel scan -> CSR offsets ----------------------
// block sums (coalesced) + fused dis
__global__ void k_blocksum(int n) {
    __shared__ int sh[256];
    int i = blockIdx.x * 256 + threadIdx.x;
    int c = (i < n) ? g_count[i] : 0;
    if (i < n) g_dis[i] = rsqrtf((float)(c + 1));   // +1 self-loop
    sh[threadIdx.x] = c;
    __syncthreads();
#pragma unroll
    for (int off = 128; off > 0; off >>= 1) {
        if (threadIdx.x < off) sh[threadIdx.x] += sh[threadIdx.x + off];
        __syncthreads();
    }
    if (threadIdx.x == 0) g_bsum[blockIdx.x] = sh[0];
}

// scan the (<=512) block sums in one block
__global__ void k_scanb(int nb) {
    __shared__ int sm[512];
    int t = threadIdx.x;
    sm[t] = (t < nb) ? g_bsum[t] : 0;
    __syncthreads();
    for (int off = 1; off < 512; off <<= 1) {
        int v = (t >= off) ? sm[t - off] : 0;
        __syncthreads();
        sm[t] += v;
        __syncthreads();
    }
    if (t < nb) g_bpre[t] = (t > 0) ? sm[t - 1] : 0;
}

// per-block exclusive scan + base
__global__ void k_offsets(int n) {
    __shared__ int sm[256];
    int t = threadIdx.x;
    int i = blockIdx.x * 256 + t;
    int c = (i < n) ? g_count[i] : 0;
    sm[t] = c;
    __syncthreads();
    for (int off = 1; off < 256; off <<= 1) {
        int v = (t >= off) ? sm[t - off] : 0;
        __syncthreads();
        sm[t] += v;
        __syncthreads();
    }
    if (i < n) {
        int excl = sm[t] - c + g_bpre[blockIdx.x];
        g_rowstart[i] = excl;
        g_cursor[i]   = excl;
    }
}

__global__ void k_fill(const int* __restrict__ ei, int e) {
    int i = blockIdx.x * blockDim.x + threadIdx.x;
    if (i < e) {
        int s = ei[i];
        int d = ei[e + i];
        int pos = atomicAdd(&g_cursor[d], 1);
        g_csr[pos] = s;
    }
}

// ---------------- phase 3: gather SpMM (warp per node, MLP=4) ----------------
__global__ void k_spmm(const float* __restrict__ x, int n, int e) {
    int warp = (blockIdx.x * blockDim.x + threadIdx.x) >> 5;
    if (warp >= n) return;
    int lane = threadIdx.x & 31;

    const float4* xr = (const float4*)x;
    float di = g_dis[warp];
    float4 a = xr[(size_t)warp * 32 + lane];
    float sn = di * di;                              // self-loop norm
    float4 acc = make_float4(sn * a.x, sn * a.y, sn * a.z, sn * a.w);

    int j   = g_rowstart[warp];
    int end = (warp + 1 < n) ? g_rowstart[warp + 1] : e;

    for (; j + 4 <= end; j += 4) {
        int i0 = __ldg(&g_csr[j + 0]);
        int i1 = __ldg(&g_csr[j + 1]);
        int i2 = __ldg(&g_csr[j + 2]);
        int i3 = __ldg(&g_csr[j + 3]);
        float w0 = di * __ldg(&g_dis[i0]);
        float w1 = di * __ldg(&g_dis[i1]);
        float w2 = di * __ldg(&g_dis[i2]);
        float w3 = di * __ldg(&g_dis[i3]);
        float4 v0 = xr[(size_t)i0 * 32 + lane];
        float4 v1 = xr[(size_t)i1 * 32 + lane];
        float4 v2 = xr[(size_t)i2 * 32 + lane];
        float4 v3 = xr[(size_t)i3 * 32 + lane];
        acc.x += w0 * v0.x + w1 * v1.x + w2 * v2.x + w3 * v3.x;
        acc.y += w0 * v0.y + w1 * v1.y + w2 * v2.y + w3 * v3.y;
        acc.z += w0 * v0.z + w1 * v1.z + w2 * v2.z + w3 * v3.z;
        acc.w += w0 * v0.w + w1 * v1.w + w2 * v2.w + w3 * v3.w;
    }
    for (; j < end; ++j) {
        int s = __ldg(&g_csr[j]);
        float w = di * __ldg(&g_dis[s]);
        float4 v = xr[(size_t)s * 32 + lane];
        acc.x += w * v.x; acc.y += w * v.y;
        acc.z += w * v.z; acc.w += w * v.w;
    }
    ((float4*)g_h)[(size_t)warp * 32 + lane] = acc;
}

// ---------------- phase 4: tf32 WMMA GEMM + fused epilogue -------------------
// out = relu( C1*(h + x0) + BETA * ([h|x0] @ [W1;W2]) ),  [N,256]x[256,128]
#define BM 128
#define BN 128
#define BK 32
#define LDA 40      // BK+8, 160B multiple of 16B
#define LDB 136     // BN+8, 544B multiple of 16B

__global__ __launch_bounds__(256)
void k_gemm(const float* __restrict__ x0,
            const float* __restrict__ w1, const float* __restrict__ w2,
            float* __restrict__ out, int n) {
    extern __shared__ float smem[];
    float* sA = smem;                 // BM x LDA = 5120 floats
    float* sB = smem + BM * LDA;      // BK x LDB = 4352 floats (total 37888B)
    float* sC = smem;                 // reused after mainloop: 128x128 (64KB)

    const float BETA = 0.6931471805599453f;
    const float C1   = 0.15342640972002733f;   // (1-a)(1-b) = a(1-b), a=0.5

    int tid  = threadIdx.x;
    int bm   = blockIdx.x * BM;
    int warp = tid >> 5;
    int wm   = (warp >> 1) * 32;      // 0,32,64,96
    int wn   = (warp & 1) * 64;       // 0,64

    wmma::fragment<wmma::accumulator, 16, 16, 8, float> c[2][4];
#pragma unroll
    for (int i = 0; i < 2; ++i)
#pragma unroll
        for (int jf = 0; jf < 4; ++jf) wmma::fill_fragment(c[i][jf], 0.0f);

    int ar = tid >> 3;                // A loader: row 0..31
    int ac = (tid & 7) * 4;           // col 0..28
    int br = tid >> 5;                // B loader: k 0..7
    int bc = (tid & 31) * 4;          // col 0..124

    for (int k0 = 0; k0 < 256; k0 += BK) {
        const float* Ap; const float* Bp; int kk0;
        if (k0 < 128) { Ap = g_h; Bp = w1; kk0 = k0; }
        else          { Ap = x0;  Bp = w2; kk0 = k0 - 128; }

#pragma unroll
        for (int s = 0; s < 4; ++s) {
            int r  = ar + s * 32;
            int gi = bm + r;
            float4 v = make_float4(0.f, 0.f, 0.f, 0.f);
            if (gi < n) v = *(const float4*)(Ap + (size_t)gi * CDIM + kk0 + ac);
            *(float4*)&sA[r * LDA + ac] = v;
        }
#pragma unroll
        for (int s = 0; s < 4; ++s) {
            int r = br + s * 8;
            *(float4*)&sB[r * LDB + bc] =
                *(const float4*)(Bp + (size_t)(kk0 + r) * CDIM + bc);
        }
        __syncthreads();

#pragma unroll
        for (int kk = 0; kk < BK; kk += 8) {
            wmma::fragment<wmma::matrix_a, 16, 16, 8, wmma::precision::tf32,
                           wmma::row_major> af[2];
            wmma::fragment<wmma::matrix_b, 16, 16, 8, wmma::precision::tf32,
                           wmma::row_major> bf[4];
#pragma unroll
            for (int i = 0; i < 2; ++i) {
                wmma::load_matrix_sync(af[i], &sA[(wm + 16 * i) * LDA + kk], LDA);
#pragma unroll
                for (int t = 0; t < af[i].num_elements; ++t)
                    af[i].x[t] = wmma::__float_to_tf32(af[i].x[t]);
            }
#pragma unroll
            for (int jf = 0; jf < 4; ++jf) {
                wmma::load_matrix_sync(bf[jf], &sB[kk * LDB + wn + 16 * jf], LDB);
#pragma unroll
                for (int t = 0; t < bf[jf].num_elements; ++t)
                    bf[jf].x[t] = wmma::__float_to_tf32(bf[jf].x[t]);
            }
#pragma unroll
            for (int i = 0; i < 2; ++i)
#pragma unroll
                for (int jf = 0; jf < 4; ++jf)
                    wmma::mma_sync(c[i][jf], af[i], bf[jf], c[i][jf]);
        }
        __syncthreads();
    }

    // park C in smem, then fused epilogue
#pragma unroll
    for (int i = 0; i < 2; ++i)
#pragma unroll
        for (int jf = 0; jf < 4; ++jf)
            wmma::store_matrix_sync(&sC[(wm + 16 * i) * 128 + wn + 16 * jf],
                                    c[i][jf], 128, wmma::mem_row_major);
    __syncthreads();

    for (int idx = tid; idx < BM * 32; idx += 256) {   // float4 granularity
        int r  = idx >> 5;
        int c4 = (idx & 31) * 4;
        int gi = bm + r;
        if (gi < n) {
            float4 g = *(float4*)&sC[r * 128 + c4];
            float4 h = *(const float4*)(g_h + (size_t)gi * CDIM + c4);
            float4 p = *(const float4*)(x0  + (size_t)gi * CDIM + c4);
            float4 o;
            o.x = fmaxf(BETA * g.x + C1 * (h.x + p.x), 0.f);
            o.y = fmaxf(BETA * g.y + C1 * (h.y + p.y), 0.f);
            o.z = fmaxf(BETA * g.z + C1 * (h.z + p.z), 0.f);
            o.w = fmaxf(BETA * g.w + C1 * (h.w + p.w), 0.f);
            *(float4*)(out + (size_t)gi * CDIM + c4) = o;
        }
    }
}

// ---------------- launch -----------------------------------------------------
extern "C" void kernel_launch(void* const* d_in, const int* in_sizes, int n_in,
                              void* d_out, int out_size) {
    const float* x  = (const float*)d_in[0];
    const float* x0 = (const float*)d_in[1];
    const float* w1 = (const float*)d_in[2];
    const float* w2 = (const float*)d_in[3];
    const int*   ei = (const int*)d_in[4];
    float* out = (float*)d_out;

    int n = in_sizes[0] / CDIM;
    int e = in_sizes[4] / 2;

    int nb = (n + 255) / 256;
    int eb = (e + 255) / 256;

    static int smem_set = 0;
    if (!smem_set) {
        cudaFuncSetAttribute(k_gemm, cudaFuncAttributeMaxDynamicSharedMemorySize,
                             128 * 128 * 4);
        smem_set = 1;
    }

    k_zero<<<nb, 256>>>(n);
    k_degree<<<eb, 256>>>(ei, e);
    k_blocksum<<<nb, 256>>>(n);
    k_scanb<<<1, 512>>>(nb);
    k_offsets<<<nb, 256>>>(n);
    k_fill<<<eb, 256>>>(ei, e);

    k_spmm<<<(n * 32 + 255) / 256, 256>>>(x, n, e);

    k_gemm<<<(n + BM - 1) / BM, 256, 128 * 128 * 4>>>(x0, w1, w2, out, n);
}

// round 4
// speedup vs baseline: 2.3482x; 1.1829x over previous
#include <cuda_runtime.h>
#include <mma.h>
#include <cstdint>
#include <math.h>

using namespace nvcuda;

#define NMAX 100000
#define EMAX 800000
#define CDIM 128
#define KDIM 256

#define BETA_F 0.6931471805599453f
#define C1_F   0.15342640972002733f

// ---------------- scratch ----------------------------------------------------
__device__ int   g_count[NMAX];
__device__ float g_dis[NMAX];
__device__ int   g_rowstart[NMAX];
__device__ int   g_cursor[NMAX];
__device__ int   g_csr[EMAX];
__device__ int   g_bsum[512];
__device__ int   g_bpre[512];
__device__ int   g_tick;
__device__ float g_h[(size_t)NMAX * CDIM];
__device__ float g_bt[KDIM * CDIM];   // [k][n], pre-scaled by BETA, tf32-rounded

// ---------------- helpers ----------------------------------------------------
__device__ __forceinline__ uint32_t cvta_s(const void* p) {
    uint32_t a;
    asm("{ .reg .u64 t; cvta.to.shared.u64 t, %1; cvt.u32.u64 %0, t; }"
        : "=r"(a) : "l"(p));
    return a;
}

__device__ __forceinline__ void cp_async16(uint32_t dst, const void* src,
                                           uint32_t src_bytes) {
    asm volatile("cp.async.ca.shared.global [%0], [%1], 16, %2;"
                 :: "r"(dst), "l"(src), "r"(src_bytes) : "memory");
}

// ---------------- prep: zero counts + transform W ----------------------------
__global__ void k_prep(const float* __restrict__ w1, const float* __restrict__ w2,
                       int n) {
    int i = blockIdx.x * blockDim.x + threadIdx.x;
    if (i < n) g_count[i] = 0;
    if (i < KDIM * CDIM) {
        int nn = i & 127;
        int kk = i >> 7;
        float v = (kk < 128) ? w1[kk * 128 + nn] : w2[(kk - 128) * 128 + nn];
        g_bt[i] = wmma::__float_to_tf32(BETA_F * v);
    }
}

__global__ void k_degree(const int* __restrict__ ei, int e) {
    int i = blockIdx.x * blockDim.x + threadIdx.x;
    if (i < e) atomicAdd(&g_count[ei[e + i]], 1);
}

// block sums + dis; last block scans the block sums
__global__ void k_blockscan(int n, int nb) {
    __shared__ int sh[256];
    __shared__ int flag;
    __shared__ int sm[512];
    int t = threadIdx.x;
    int i = blockIdx.x * 256 + t;
    int c = (i < n) ? g_count[i] : 0;
    if (i < n) g_dis[i] = rsqrtf((float)(c + 1));
    sh[t] = c;
    __syncthreads();
#pragma unroll
    for (int off = 128; off > 0; off >>= 1) {
        if (t < off) sh[t] += sh[t + off];
        __syncthreads();
    }
    if (t == 0) {
        g_bsum[blockIdx.x] = sh[0];
        __threadfence();
        int old = atomicAdd(&g_tick, 1);
        flag = (old == nb - 1);
    }
    __syncthreads();
    if (flag) {
        __threadfence();
        sm[t]       = (t < nb)       ? g_bsum[t]       : 0;
        sm[t + 256] = (t + 256 < nb) ? g_bsum[t + 256] : 0;
        __syncthreads();
        for (int off = 1; off < 512; off <<= 1) {
            int a = (t >= off) ? sm[t - off] : 0;
            int b = (t + 256 >= off) ? sm[t + 256 - off] : 0;
            __syncthreads();
            sm[t] += a;
            sm[t + 256] += b;
            __syncthreads();
        }
        if (t < nb)       g_bpre[t]       = (t > 0) ? sm[t - 1] : 0;
        if (t + 256 < nb) g_bpre[t + 256] = sm[t + 255];
        if (t == 0) g_tick = 0;
    }
}

__global__ void k_offsets(int n) {
    __shared__ int sm[256];
    int t = threadIdx.x;
    int i = blockIdx.x * 256 + t;
    int c = (i < n) ? g_count[i] : 0;
    sm[t] = c;
    __syncthreads();
    for (int off = 1; off < 256; off <<= 1) {
        int v = (t >= off) ? sm[t - off] : 0;
        __syncthreads();
        sm[t] += v;
        __syncthreads();
    }
    if (i < n) {
        int excl = sm[t] - c + g_bpre[blockIdx.x];
        g_rowstart[i] = excl;
        g_cursor[i]   = excl;
    }
}

__global__ void k_fill(const int* __restrict__ ei, int e) {
    int i = blockIdx.x * blockDim.x + threadIdx.x;
    if (i < e) {
        int s = ei[i];
        int d = ei[e + i];
        int pos = atomicAdd(&g_cursor[d], 1);
        g_csr[pos] = s;
    }
}

// ---------------- gather SpMM (warp per node, MLP=4) -------------------------
__global__ void k_spmm(const float* __restrict__ x, int n, int e) {
    int warp = (blockIdx.x * blockDim.x + threadIdx.x) >> 5;
    if (warp >= n) return;
    int lane = threadIdx.x & 31;

    const float4* xr = (const float4*)x;
    float di = g_dis[warp];
    float4 a = xr[(size_t)warp * 32 + lane];
    float sn = di * di;
    float4 acc = make_float4(sn * a.x, sn * a.y, sn * a.z, sn * a.w);

    int j   = g_rowstart[warp];
    int end = (warp + 1 < n) ? g_rowstart[warp + 1] : e;

    for (; j + 4 <= end; j += 4) {
        int i0 = __ldg(&g_csr[j + 0]);
        int i1 = __ldg(&g_csr[j + 1]);
        int i2 = __ldg(&g_csr[j + 2]);
        int i3 = __ldg(&g_csr[j + 3]);
        float w0 = di * __ldg(&g_dis[i0]);
        float w1 = di * __ldg(&g_dis[i1]);
        float w2 = di * __ldg(&g_dis[i2]);
        float w3 = di * __ldg(&g_dis[i3]);
        float4 v0 = xr[(size_t)i0 * 32 + lane];
        float4 v1 = xr[(size_t)i1 * 32 + lane];
        float4 v2 = xr[(size_t)i2 * 32 + lane];
        float4 v3 = xr[(size_t)i3 * 32 + lane];
        acc.x += w0 * v0.x + w1 * v1.x + w2 * v2.x + w3 * v3.x;
        acc.y += w0 * v0.y + w1 * v1.y + w2 * v2.y + w3 * v3.y;
        acc.z += w0 * v0.z + w1 * v1.z + w2 * v2.z + w3 * v3.z;
        acc.w += w0 * v0.w + w1 * v1.w + w2 * v2.w + w3 * v3.w;
    }
    for (; j < end; ++j) {
        int s = __ldg(&g_csr[j]);
        float w = di * __ldg(&g_dis[s]);
        float4 v = xr[(size_t)s * 32 + lane];
        acc.x += w * v.x; acc.y += w * v.y;
        acc.z += w * v.z; acc.w += w * v.w;
    }
    ((float4*)g_h)[(size_t)warp * 32 + lane] = acc;
}

// ---------------- tf32 WMMA GEMM, cp.async double-buffered -------------------
// out = relu( C1*(h+x0) + [h|x0] @ g_bt ),  [N,256]x[256,128]
#define BM 128
#define BN 128
#define BK 32
#define LDA 40      // 160B row pitch
#define LDB 136     // 544B row pitch
#define NT 8        // K-tiles

// per-stage: A 128*40*4 = 20480B, B 32*136*4 = 17408B
#define STG_A 20480
#define STG_B 17408
#define STG (STG_A + STG_B)
#define GSMEM_BYTES (2 * STG)   // 75776; C-park (64KB) reuses this space

__global__ __launch_bounds__(256)
void k_gemm(const float* __restrict__ x0, float* __restrict__ out, int n) {
    extern __shared__ float smem[];
    uint32_t sbase = cvta_s(smem);

    int tid  = threadIdx.x;
    int warp = tid >> 5;
    int bm   = blockIdx.x * BM;
    int wm   = (warp >> 1) * 32;
    int wn   = (warp & 1) * 64;

    // loader indices
    int arA = tid >> 3;            // 0..31 (row group), rows r = arA + 32*q
    int acA = (tid & 7) * 4;       // col 0..28
    int brB = tid >> 5;            // 0..7, rows kb = brB + 8*q
    int bcB = (tid & 31) * 4;      // col 0..124

    wmma::fragment<wmma::accumulator, 16, 16, 8, float> c[2][4];
#pragma unroll
    for (int i = 0; i < 2; ++i)
#pragma unroll
        for (int jf = 0; jf < 4; ++jf) wmma::fill_fragment(c[i][jf], 0.0f);

    auto issue_stage = [&](int s, int kt) {
        uint32_t aB = sbase + s * STG;
        uint32_t bB = aB + STG_A;
        const float* Ap = (kt < 4) ? g_h : x0;
        int ak0 = (kt & 3) * 32;
#pragma unroll
        for (int q = 0; q < 4; ++q) {
            int r  = arA + 32 * q;
            int gi = bm + r;
            const float* src = Ap + (size_t)gi * CDIM + ak0 + acA;
            cp_async16(aB + (uint32_t)(r * LDA + acA) * 4, src,
                       (gi < n) ? 16u : 0u);
            int kb = brB + 8 * q;
            const float* bsrc = g_bt + (size_t)(kt * 32 + kb) * CDIM + bcB;
            cp_async16(bB + (uint32_t)(kb * LDB + bcB) * 4, bsrc, 16u);
        }
        asm volatile("cp.async.commit_group;" ::: "memory");
    };

    issue_stage(0, 0);

    for (int kt = 0; kt < NT; ++kt) {
        if (kt + 1 < NT) {
            issue_stage((kt + 1) & 1, kt + 1);
            asm volatile("cp.async.wait_group 1;" ::: "memory");
        } else {
            asm volatile("cp.async.wait_group 0;" ::: "memory");
        }
        __syncthreads();

        float* sA = smem + (kt & 1) * (STG / 4);
        float* sB = sA + STG_A / 4;

#pragma unroll
        for (int kk = 0; kk < BK; kk += 8) {
            wmma::fragment<wmma::matrix_a, 16, 16, 8, wmma::precision::tf32,
                           wmma::row_major> af[2];
            wmma::fragment<wmma::matrix_b, 16, 16, 8, wmma::precision::tf32,
                           wmma::row_major> bf[4];
#pragma unroll
            for (int i = 0; i < 2; ++i) {
                wmma::load_matrix_sync(af[i], &sA[(wm + 16 * i) * LDA + kk], LDA);
#pragma unroll
                for (int t = 0; t < af[i].num_elements; ++t)
                    af[i].x[t] = wmma::__float_to_tf32(af[i].x[t]);
            }
#pragma unroll
            for (int jf = 0; jf < 4; ++jf)
                wmma::load_matrix_sync(bf[jf], &sB[kk * LDB + wn + 16 * jf], LDB);
            // B pre-rounded to tf32 in k_prep: no conversion needed
#pragma unroll
            for (int i = 0; i < 2; ++i)
#pragma unroll
                for (int jf = 0; jf < 4; ++jf)
                    wmma::mma_sync(c[i][jf], af[i], bf[jf], c[i][jf]);
        }
        __syncthreads();
    }

    // park C in smem (reuses stage buffers), fused epilogue
    float* sC = smem;
#pragma unroll
    for (int i = 0; i < 2; ++i)
#pragma unroll
        for (int jf = 0; jf < 4; ++jf)
            wmma::store_matrix_sync(&sC[(wm + 16 * i) * 128 + wn + 16 * jf],
                                    c[i][jf], 128, wmma::mem_row_major);
    __syncthreads();

    for (int idx = tid; idx < BM * 32; idx += 256) {
        int r  = idx >> 5;
        int c4 = (idx & 31) * 4;
        int gi = bm + r;
        if (gi < n) {
            float4 g = *(float4*)&sC[r * 128 + c4];
            float4 h = *(const float4*)(g_h + (size_t)gi * CDIM + c4);
            float4 p = *(const float4*)(x0  + (size_t)gi * CDIM + c4);
            float4 o;
            o.x = fmaxf(g.x + C1_F * (h.x + p.x), 0.f);
            o.y = fmaxf(g.y + C1_F * (h.y + p.y), 0.f);
            o.z = fmaxf(g.z + C1_F * (h.z + p.z), 0.f);
            o.w = fmaxf(g.w + C1_F * (h.w + p.w), 0.f);
            *(float4*)(out + (size_t)gi * CDIM + c4) = o;
        }
    }
}

// ---------------- launch -----------------------------------------------------
extern "C" void kernel_launch(void* const* d_in, const int* in_sizes, int n_in,
                              void* d_out, int out_size) {
    const float* x  = (const float*)d_in[0];
    const float* x0 = (const float*)d_in[1];
    const float* w1 = (const float*)d_in[2];
    const float* w2 = (const float*)d_in[3];
    const int*   ei = (const int*)d_in[4];
    float* out = (float*)d_out;

    int n = in_sizes[0] / CDIM;
    int e = in_sizes[4] / 2;
    int nb = (n + 255) / 256;
    int eb = (e + 255) / 256;

    static int attr_set = 0;
    if (!attr_set) {
        cudaFuncSetAttribute(k_gemm, cudaFuncAttributeMaxDynamicSharedMemorySize,
                             GSMEM_BYTES);
        attr_set = 1;
    }

    k_prep<<<nb, 256>>>(w1, w2, n);
    k_degree<<<eb, 256>>>(ei, e);
    k_blockscan<<<nb, 256>>>(n, nb);
    k_offsets<<<nb, 256>>>(n);
    k_fill<<<eb, 256>>>(ei, e);
    k_spmm<<<(n * 32 + 255) / 256, 256>>>(x, n, e);
    k_gemm<<<(n + BM - 1) / BM, 256, GSMEM_BYTES>>>(x0, out, n);
}